// round 2
// baseline (speedup 1.0000x reference)
#include <cuda_runtime.h>
#include <math.h>

// Problem constants
#define NB     8
#define D_IN   514
#define T_IN   4000
#define NCOLS  (NB * T_IN)     // 32000 columns (b,t)
#define T_OUT  3999
#define J_OUT  256

// Scratch: S[b][n][t]  (n = 0..511), the "ifft_data" matrix
__device__ float g_S[(size_t)NB * 512 * T_IN];          // 65.5 MB
// Transposed coefficient tables, [k][n] layout for coalesced GEMM loads
__device__ float g_ct[256 * 256];                        // cos coeffs (E)
__device__ float g_st[256 * 256];                        // sin coeffs (O)

// ---------------------------------------------------------------------------
// Table init: g_ct[k][n] = (k==0 ? 1 : 2cos(pi*n*k/256)), g_st[k][n] = 2sin(...)
// ---------------------------------------------------------------------------
__global__ void init_tables_kernel() {
    int k = blockIdx.x;
    int n = threadIdx.x;
    float x = (float)(n * k) / 256.0f;   // exact: n*k < 2^16, /256 exact
    g_ct[k * 256 + n] = (k == 0) ? 1.0f : 2.0f * cospif(x);
    g_st[k * 256 + n] = 2.0f * sinpif(x);
}

// ---------------------------------------------------------------------------
// GEMM: for n in [0,255], col in [0,32000):
//   E[n,c] = sum_k real[k,c]*ct[k][n],  O[n,c] = sum_k imag[k,c]*st[k][n]
//   S[n]   = E+O ;  S[512-n] = E-O (n>0)
// Tiles: BN=128 (grid.y=2), BC=64 (grid.x=500), BK=16. 256 threads,
// per-thread micro-tile 8n x 4c with dual accumulators (E,O).
// ---------------------------------------------------------------------------
__global__ __launch_bounds__(256) void gemm_kernel(const float* __restrict__ in) {
    __shared__ __align__(16) float sAc[16][128];
    __shared__ __align__(16) float sAs[16][128];
    __shared__ __align__(16) float sXr[16][64];
    __shared__ __align__(16) float sXi[16][64];

    const int col0 = blockIdx.x * 64;
    const int n0   = blockIdx.y * 128;
    const int tid  = threadIdx.x;
    const int tc   = tid & 15;        // 0..15 -> col group
    const int tn   = tid >> 4;        // 0..15 -> n group
    const int c4   = tc * 4;
    const int n8   = tn * 8;

    // Hoist X load addressing (invariant across k-chunks)
    const float* xbase[4];
    int xkr[4], xc[4];
#pragma unroll
    for (int p = 0; p < 4; p++) {
        int f  = tid + p * 256;
        int kr = f >> 6;              // 0..15
        int c  = f & 63;
        int gc = col0 + c;
        int b  = gc / T_IN;
        int t  = gc - b * T_IN;
        xkr[p] = kr;
        xc[p]  = c;
        xbase[p] = in + (size_t)b * D_IN * T_IN + (size_t)kr * T_IN + t;
    }

    float accE[8][4];
    float accO[8][4];
#pragma unroll
    for (int i = 0; i < 8; i++)
#pragma unroll
        for (int j = 0; j < 4; j++) { accE[i][j] = 0.0f; accO[i][j] = 0.0f; }

    for (int kk0 = 0; kk0 < 256; kk0 += 16) {
        // A tiles: 16x128 each, via float4 (512 float4 per array, 2/thread)
#pragma unroll
        for (int p = 0; p < 2; p++) {
            int f  = tid + p * 256;
            int kr = f >> 5;             // 0..15
            int nf = (f & 31) << 2;      // 0,4,...,124
            *(float4*)&sAc[kr][nf] = *(const float4*)&g_ct[(kk0 + kr) * 256 + n0 + nf];
            *(float4*)&sAs[kr][nf] = *(const float4*)&g_st[(kk0 + kr) * 256 + n0 + nf];
        }
        // X tiles: real rows d = kk0+kr (0..255), imag rows d = 257+kk0+kr (257..512)
#pragma unroll
        for (int p = 0; p < 4; p++) {
            const float* bp = xbase[p] + (size_t)kk0 * T_IN;
            sXr[xkr[p]][xc[p]] = bp[0];
            sXi[xkr[p]][xc[p]] = bp[(size_t)257 * T_IN];
        }
        __syncthreads();

#pragma unroll
        for (int k = 0; k < 16; k++) {
            float4 a0 = *(float4*)&sAc[k][n8];
            float4 a1 = *(float4*)&sAc[k][n8 + 4];
            float4 b0 = *(float4*)&sAs[k][n8];
            float4 b1 = *(float4*)&sAs[k][n8 + 4];
            float4 r4 = *(float4*)&sXr[k][c4];
            float4 i4 = *(float4*)&sXi[k][c4];
            float av[8] = {a0.x, a0.y, a0.z, a0.w, a1.x, a1.y, a1.z, a1.w};
            float bv[8] = {b0.x, b0.y, b0.z, b0.w, b1.x, b1.y, b1.z, b1.w};
            float rv[4] = {r4.x, r4.y, r4.z, r4.w};
            float iv[4] = {i4.x, i4.y, i4.z, i4.w};
#pragma unroll
            for (int i = 0; i < 8; i++)
#pragma unroll
                for (int j = 0; j < 4; j++) {
                    accE[i][j] = fmaf(av[i], rv[j], accE[i][j]);
                    accO[i][j] = fmaf(bv[i], iv[j], accO[i][j]);
                }
        }
        __syncthreads();
    }

    // Write S rows n (E+O) and 512-n (E-O)
#pragma unroll
    for (int j = 0; j < 4; j++) {
        int gc = col0 + c4 + j;
        int b  = gc / T_IN;
        int t  = gc - b * T_IN;
        size_t baseb = (size_t)b * 512 * T_IN + t;
#pragma unroll
        for (int i = 0; i < 8; i++) {
            int n = n0 + n8 + i;
            g_S[baseb + (size_t)n * T_IN] = accE[i][j] + accO[i][j];
            if (n > 0)
                g_S[baseb + (size_t)(512 - n) * T_IN] = accE[i][j] - accO[i][j];
        }
    }
}

// ---------------------------------------------------------------------------
// Row 256: S[b][256][t] = real[0] + 2*sum_{k=1..255} (-1)^k * real[k]
// ---------------------------------------------------------------------------
__global__ void row256_kernel(const float* __restrict__ in) {
    int gc = blockIdx.x * 256 + threadIdx.x;
    if (gc >= NCOLS) return;
    int b = gc / T_IN;
    int t = gc - b * T_IN;
    const float* base = in + (size_t)b * D_IN * T_IN + t;
    float acc = base[0];
#pragma unroll 8
    for (int k = 1; k < 256; k++) {
        float coef = (k & 1) ? -2.0f : 2.0f;
        acc = fmaf(coef, base[(size_t)k * T_IN], acc);
    }
    g_S[(size_t)b * 512 * T_IN + (size_t)256 * T_IN + t] = acc;
}

// ---------------------------------------------------------------------------
// Epilogue: windowed 4-frame overlap-add + flip + transpose.
// out[b, t, j] = 256 * ( win[1023-j]*S[511-j][t]   + win[767-j]*S[255-j][t-1]
//                      + win[511-j]*S[511-j][t-2] + win[255-j]*S[255-j][t-3] )
// Block: (t-tile 32) x (j-half 128) x b. SMEM-staged for coalescing both ways.
// ---------------------------------------------------------------------------
__global__ __launch_bounds__(128) void epilogue_kernel(const float* __restrict__ win,
                                                       float* __restrict__ out) {
    __shared__ float sS0[128][37];   // rows 255-j family (pad 37: conflict-free)
    __shared__ float sS1[128][37];   // rows 511-j family
    __shared__ float sw[1024];

    const int t0 = blockIdx.x * 32;
    const int jh = blockIdx.y;            // 0 or 1
    const int b  = blockIdx.z;
    const int j0 = jh * 128;
    const int part0base = 128 * (1 - jh);        // rows 255-j  -> [base, base+127]
    const int part1base = 256 + 128 * (1 - jh);  // rows 511-j
    const int tid = threadIdx.x;

    const float* Sb = g_S + (size_t)b * 512 * T_IN;

    for (int i = tid; i < 1024; i += 128) sw[i] = win[i];

    for (int idx = tid; idx < 128 * 36; idx += 128) {
        int rr = idx / 36;
        int tc = idx - rr * 36;
        int ts = t0 - 3 + tc;
        float v0 = 0.0f, v1 = 0.0f;
        if (ts >= 0 && ts < T_IN) {
            v0 = Sb[(size_t)(part0base + rr) * T_IN + ts];
            v1 = Sb[(size_t)(part1base + rr) * T_IN + ts];
        }
        sS0[rr][tc] = v0;
        sS1[rr][tc] = v1;
    }
    __syncthreads();

    const int j  = j0 + tid;
    const int rr = 127 - tid;       // local row for both 511-j and 255-j
    const float w1 = 256.0f * sw[1023 - j];
    const float w2 = 256.0f * sw[767 - j];
    const float w3 = 256.0f * sw[511 - j];
    const float w4 = 256.0f * sw[255 - j];

    float* ob = out + ((size_t)b * T_OUT + t0) * 256 + j;
#pragma unroll 4
    for (int dt = 0; dt < 32; dt++) {
        int t = t0 + dt;
        if (t >= T_OUT) break;
        float v = w1 * sS1[rr][3 + dt]
                + w2 * sS0[rr][2 + dt]
                + w3 * sS1[rr][1 + dt]
                + w4 * sS0[rr][dt];
        ob[(size_t)dt * 256] = v;
    }
}

// ---------------------------------------------------------------------------
extern "C" void kernel_launch(void* const* d_in, const int* in_sizes, int n_in,
                              void* d_out, int out_size) {
    const float* in  = (const float*)d_in[0];   // (8, 514, 4000) f32
    const float* win = (const float*)d_in[1];   // (1024,) f32
    float* out = (float*)d_out;                 // (8, 3999*256) f32

    init_tables_kernel<<<256, 256>>>();

    dim3 gG(500, 2);             // 500 col tiles x 2 n tiles
    gemm_kernel<<<gG, 256>>>(in);

    row256_kernel<<<(NCOLS + 255) / 256, 256>>>(in);

    dim3 gE(125, 2, NB);         // t tiles x j halves x batch
    epilogue_kernel<<<gE, 128>>>(win, out);
}